// round 13
// baseline (speedup 1.0000x reference)
#include <cuda_runtime.h>
#include <cuda_bf16.h>
#include <cstdint>
#include <math.h>

#define D_MODEL   1024
#define N_HEADS   16
#define HEAD_DIM  64
#define BATCH     2
#define TLEN      2048
#define WINDOW    128
#define MROWS     (BATCH * TLEN)          // 4096
#define QKV_N     (MROWS * D_MODEL)       // 4194304

// bf16 scratch
__device__ __nv_bfloat16 g_qh[QKV_N], g_ql[QKV_N];          // input query split
__device__ __nv_bfloat16 g_wh[4][D_MODEL * D_MODEL];
__device__ __nv_bfloat16 g_wl[4][D_MODEL * D_MODEL];
__device__ __nv_bfloat16 g_ah[QKV_N], g_al[QKV_N];          // attn out split
// rope'd q (pre-scaled), k, v splits in [b,h,t,d]
__device__ __nv_bfloat16 g_xqh[QKV_N], g_xql[QKV_N];
__device__ __nv_bfloat16 g_xkh[QKV_N], g_xkl[QKV_N];
__device__ __nv_bfloat16 g_xvh[QKV_N], g_xvl[QKV_N];

// ---------------------------------------------------------------------------
__device__ __forceinline__ uint32_t smem_u32(const void* p) {
    uint32_t a;
    asm("{ .reg .u64 t; cvta.to.shared.u64 t, %1; cvt.u32.u64 %0, t; }"
        : "=r"(a) : "l"(p));
    return a;
}

#define CP_ASYNC16(dst, src) \
    asm volatile("cp.async.cg.shared.global [%0], [%1], 16;" :: "r"(dst), "l"(src))
#define CP_COMMIT()  asm volatile("cp.async.commit_group;" ::: "memory")
#define CP_WAIT(n)   asm volatile("cp.async.wait_group %0;" :: "n"(n) : "memory")

#define LDSM4(r0, r1, r2, r3, a) \
    asm volatile("ldmatrix.sync.aligned.m8n8.x4.shared.b16 {%0,%1,%2,%3}, [%4];" \
                 : "=r"(r0), "=r"(r1), "=r"(r2), "=r"(r3) : "r"(a))
#define LDSM4T(r0, r1, r2, r3, a) \
    asm volatile("ldmatrix.sync.aligned.m8n8.x4.trans.shared.b16 {%0,%1,%2,%3}, [%4];" \
                 : "=r"(r0), "=r"(r1), "=r"(r2), "=r"(r3) : "r"(a))

__device__ __forceinline__ void mma_bf16(float* d, uint32_t a0, uint32_t a1,
                                         uint32_t a2, uint32_t a3,
                                         uint32_t b0, uint32_t b1) {
    asm volatile(
        "mma.sync.aligned.m16n8k16.row.col.f32.bf16.bf16.f32 "
        "{%0,%1,%2,%3}, {%4,%5,%6,%7}, {%8,%9}, {%0,%1,%2,%3};"
        : "+f"(d[0]), "+f"(d[1]), "+f"(d[2]), "+f"(d[3])
        : "r"(a0), "r"(a1), "r"(a2), "r"(a3), "r"(b0), "r"(b1));
}

__device__ __forceinline__ void packsplit(float x, float y,
                                          uint32_t& h, uint32_t& l) {
    __nv_bfloat16 hx = __float2bfloat16(x), hy = __float2bfloat16(y);
    __nv_bfloat16 lx = __float2bfloat16(x - __bfloat162float(hx));
    __nv_bfloat16 ly = __float2bfloat16(y - __bfloat162float(hy));
    h = (uint32_t)__bfloat16_as_ushort(hx) | ((uint32_t)__bfloat16_as_ushort(hy) << 16);
    l = (uint32_t)__bfloat16_as_ushort(lx) | ((uint32_t)__bfloat16_as_ushort(ly) << 16);
}

// ---------------------------------------------------------------------------
// fp32 -> (bf16 hi, bf16 lo) split: 0=query, 1..4=W
// ---------------------------------------------------------------------------
template <int DST>
__global__ __launch_bounds__(256) void split_kernel(const float* __restrict__ src, int n4)
{
    __nv_bfloat16 *dh, *dl;
    if (DST == 0) { dh = g_qh; dl = g_ql; }
    else          { dh = g_wh[DST - 1]; dl = g_wl[DST - 1]; }
    const int i = blockIdx.x * 256 + threadIdx.x;
    if (i >= n4) return;
    float4 x = ((const float4*)src)[i];
    uint32_t h0, l0, h1, l1;
    packsplit(x.x, x.y, h0, l0);
    packsplit(x.z, x.w, h1, l1);
    ((uint2*)dh)[i] = make_uint2(h0, h1);
    ((uint2*)dl)[i] = make_uint2(l0, l1);
}

// ---------------------------------------------------------------------------
// bf16 mma.sync split GEMM (validated R11).
// MODE 1: A=query splits; z selects W; epilogue: rope (z<2), q-scale (z=0),
//         write bf16 hi/lo splits to g_x{q,k,v}{h,l} in [b,h,t,d].
// MODE 0: A=attn splits (g_ah/g_al); W=Wo; +bias; fp32 row-major out.
// ---------------------------------------------------------------------------
#define PITCH   40
#define MATSZ   (128 * PITCH)
#define STAGEB  (4 * MATSZ * 2)
#define GSMEM   (2 * STAGEB)

template <int MODE>
__global__ __launch_bounds__(256, 1) void tc_gemm(const float* __restrict__ bias,
                                                  float* __restrict__ Cout)
{
    extern __shared__ __nv_bfloat16 sm[];
    const uint32_t sb = smem_u32(sm);
    const int tid  = threadIdx.x;
    const int lane = tid & 31, warp = tid >> 5;
    const int z    = (MODE == 1) ? blockIdx.z : 3;
    const int m0   = blockIdx.y * 128;
    const int n0   = blockIdx.x * 128;
    const int wm   = (warp >> 1) * 32;
    const int wn   = (warp & 1) * 64;

    const __nv_bfloat16* Ah = (MODE == 1) ? g_qh : g_ah;
    const __nv_bfloat16* Al = (MODE == 1) ? g_ql : g_al;
    const __nv_bfloat16* Wh = g_wh[z];
    const __nv_bfloat16* Wl = g_wl[z];
    const __nv_bfloat16* mats[4] = {Ah, Al, Wh, Wl};

    float acc[2][8][4];
#pragma unroll
    for (int mi = 0; mi < 2; mi++)
#pragma unroll
        for (int ni = 0; ni < 8; ni++)
#pragma unroll
            for (int e = 0; e < 4; e++) acc[mi][ni][e] = 0.f;

    auto load_stage = [&](int buf, int k0) {
#pragma unroll
        for (int it = 0; it < 8; it++) {
            const int i   = tid + it * 256;
            const int mat = i >> 9;
            const int r   = (i >> 2) & 127;
            const int c4  = i & 3;
            const uint32_t dst = sb + buf * STAGEB +
                                 (mat * MATSZ + r * PITCH + c4 * 8) * 2;
            const int grow = (mat < 2) ? (m0 + r) : (n0 + r);
            const __nv_bfloat16* src = mats[mat] + (size_t)grow * D_MODEL + k0 + c4 * 8;
            CP_ASYNC16(dst, src);
        }
        CP_COMMIT();
    };

    load_stage(0, 0);

    for (int ch = 0; ch < 32; ch++) {
        const int buf = ch & 1;
        if (ch + 1 < 32) load_stage(buf ^ 1, (ch + 1) * 32);
        if (ch + 1 < 32) CP_WAIT(1); else CP_WAIT(0);
        __syncthreads();

        const uint32_t base = sb + buf * STAGEB;
#pragma unroll
        for (int ks = 0; ks < 2; ks++) {
            const int kk = ks * 16;
            uint32_t ah[2][4], al[2][4];
#pragma unroll
            for (int mi = 0; mi < 2; mi++) {
                const uint32_t ra = (uint32_t)((wm + mi * 16 + (lane & 15)) * PITCH
                                    + kk + ((lane >> 4) << 3)) * 2;
                LDSM4(ah[mi][0], ah[mi][1], ah[mi][2], ah[mi][3], base + 0 * MATSZ * 2 + ra);
                LDSM4(al[mi][0], al[mi][1], al[mi][2], al[mi][3], base + 1 * MATSZ * 2 + ra);
            }
            uint32_t bh[8][2], bl[8][2];
#pragma unroll
            for (int ng = 0; ng < 8; ng += 2) {
                const uint32_t rb = (uint32_t)((wn + ng * 8 + (lane & 7) + ((lane >> 4) << 3)) * PITCH
                                    + kk + (((lane >> 3) & 1) << 3)) * 2;
                LDSM4(bh[ng][0], bh[ng][1], bh[ng + 1][0], bh[ng + 1][1],
                      base + 2 * MATSZ * 2 + rb);
                LDSM4(bl[ng][0], bl[ng][1], bl[ng + 1][0], bl[ng + 1][1],
                      base + 3 * MATSZ * 2 + rb);
            }
#pragma unroll
            for (int mi = 0; mi < 2; mi++)
#pragma unroll
                for (int ni = 0; ni < 8; ni++) {
                    mma_bf16(acc[mi][ni], ah[mi][0], ah[mi][1], ah[mi][2], ah[mi][3],
                             bh[ni][0], bh[ni][1]);
                    mma_bf16(acc[mi][ni], ah[mi][0], ah[mi][1], ah[mi][2], ah[mi][3],
                             bl[ni][0], bl[ni][1]);
                    mma_bf16(acc[mi][ni], al[mi][0], al[mi][1], al[mi][2], al[mi][3],
                             bh[ni][0], bh[ni][1]);
                }
        }
        __syncthreads();
    }

    // ---- epilogue ----
    const float coef = -logf(10000.0f) / 32.0f;
#pragma unroll
    for (int mi = 0; mi < 2; mi++) {
#pragma unroll
        for (int r8 = 0; r8 < 2; r8++) {
            const int m = m0 + wm + mi * 16 + (lane >> 2) + r8 * 8;
            const int t = m & (TLEN - 1);
            const int b = m >> 11;

            if (MODE == 1) {
                if (z < 2) {
#pragma unroll
                    for (int ni = 0; ni < 4; ni++)
#pragma unroll
                        for (int e = 0; e < 2; e++) {
                            const int dd = ni * 8 + ((lane & 3) << 1) + e;
                            float sn, cs;
                            sincosf((float)t * expf((float)dd * coef), &sn, &cs);
                            const float x0 = acc[mi][ni][r8 * 2 + e];
                            const float x1 = acc[mi][ni + 4][r8 * 2 + e];
                            acc[mi][ni][r8 * 2 + e]     = x0 * cs - x1 * sn;
                            acc[mi][ni + 4][r8 * 2 + e] = x1 * cs + x0 * sn;
                        }
                }
                __nv_bfloat16* dh = (z == 0) ? g_xqh : (z == 1) ? g_xkh : g_xvh;
                __nv_bfloat16* dl = (z == 0) ? g_xql : (z == 1) ? g_xkl : g_xvl;
                const float sc = (z == 0) ? 0.125f : 1.0f;   // fold sm_scale into q
                const int h = blockIdx.x * 2 + (warp & 1);
                const size_t off = (((size_t)b * N_HEADS + h) * TLEN + t) * HEAD_DIM;
#pragma unroll
                for (int ni = 0; ni < 8; ni++) {
                    const int d0 = ni * 8 + ((lane & 3) << 1);
                    uint32_t uh, ul;
                    packsplit(acc[mi][ni][r8 * 2] * sc, acc[mi][ni][r8 * 2 + 1] * sc, uh, ul);
                    *(uint32_t*)(dh + off + d0) = uh;
                    *(uint32_t*)(dl + off + d0) = ul;
                }
            } else {
                const size_t off = (size_t)m * D_MODEL + n0 + wn;
#pragma unroll
                for (int ni = 0; ni < 8; ni++) {
                    const int d0 = ni * 8 + ((lane & 3) << 1);
                    *(float2*)&Cout[off + d0] =
                        make_float2(acc[mi][ni][r8 * 2]     + __ldg(&bias[n0 + wn + d0]),
                                    acc[mi][ni][r8 * 2 + 1] + __ldg(&bias[n0 + wn + d0 + 1]));
                }
            }
        }
    }
}

// ---------------------------------------------------------------------------
// Tensor-core sliding-window attention.
// Block: 128 queries x (h,b). 8 warps, warp = 16 queries x all keys.
// K/V window [q0-128, q0+128) in smem, two 128-key chunks, online softmax.
// S = Qh.Kh + Qh.Kl + Ql.Kh ; O = Ph.Vh + Pl.Vh + Ph.Vl.
// Outputs bf16 hi/lo splits to g_ah/g_al (input of Wo gemm).
// ---------------------------------------------------------------------------
#define APITCH 72
#define QH0 0
#define QL0 9216          // 128*72
#define KH0 18432
#define KL0 36864
#define VH0 55296
#define VL0 73728
#define ASMEM (92160 * 2) // 184320 B

__global__ __launch_bounds__(256, 1) void attn_mma()
{
    extern __shared__ __nv_bfloat16 smA[];
    const uint32_t sb = smem_u32(smA);
    const int tid = threadIdx.x, lane = tid & 31, w = tid >> 5;
    const int q0 = blockIdx.x * 128;
    const int h  = blockIdx.y, b = blockIdx.z;
    const size_t hb = ((size_t)b * N_HEADS + h) * TLEN;

    // ---- load Q (128 rows) and K/V window (256 rows) ----
    {
        const __nv_bfloat16* srcQ[2]  = {g_xqh, g_xql};
        const __nv_bfloat16* srcKV[4] = {g_xkh, g_xkl, g_xvh, g_xvl};
#pragma unroll
        for (int it = 0; it < 8; it++) {
            const int idx = tid + it * 256;
            const int mat = idx >> 10, r = (idx >> 3) & 127, c = idx & 7;
            uint4 v = *(const uint4*)(srcQ[mat] + (hb + q0 + r) * 64 + c * 8);
            *(uint4*)(smA + mat * QL0 + r * APITCH + c * 8) = v;
        }
#pragma unroll
        for (int it = 0; it < 32; it++) {
            const int idx = tid + it * 256;
            const int mat = idx >> 11, r = (idx >> 3) & 255, c = idx & 7;
            const int j = q0 - 128 + r;
            uint4 v = make_uint4(0u, 0u, 0u, 0u);
            if (j >= 0) v = *(const uint4*)(srcKV[mat] + (hb + j) * 64 + c * 8);
            *(uint4*)(smA + KH0 + mat * 18432 + r * APITCH + c * 8) = v;
        }
    }
    __syncthreads();

    float oacc[8][4];
#pragma unroll
    for (int nf = 0; nf < 8; nf++)
#pragma unroll
        for (int e = 0; e < 4; e++) oacc[nf][e] = 0.f;
    float m0 = -INFINITY, m1 = -INFINITY, l0 = 0.f, l1 = 0.f;
    const int r_lo = w * 16 + (lane >> 2), r_hi = r_lo + 8;

    for (int ch = 0; ch < 2; ch++) {
        // ---- S = Q @ K^T (split) ----
        float sacc[16][4];
#pragma unroll
        for (int nf = 0; nf < 16; nf++)
#pragma unroll
            for (int e = 0; e < 4; e++) sacc[nf][e] = 0.f;

#pragma unroll
        for (int ks = 0; ks < 4; ks++) {
            const int kk = ks * 16;
            uint32_t ah[4], al[4];
            const uint32_t ra = sb + 2 * ((w * 16 + (lane & 15)) * APITCH
                                          + kk + ((lane >> 4) << 3));
            LDSM4(ah[0], ah[1], ah[2], ah[3], ra);
            LDSM4(al[0], al[1], al[2], al[3], ra + 2 * QL0);
#pragma unroll
            for (int ng = 0; ng < 16; ng += 2) {
                const uint32_t rb = sb + 2 * (KH0
                    + (ch * 128 + ng * 8 + (lane & 7) + ((lane >> 4) << 3)) * APITCH
                    + kk + (((lane >> 3) & 1) << 3));
                uint32_t kh[4], kl[4];
                LDSM4(kh[0], kh[1], kh[2], kh[3], rb);
                LDSM4(kl[0], kl[1], kl[2], kl[3], rb + 2 * (KL0 - KH0));
                mma_bf16(sacc[ng],     ah[0], ah[1], ah[2], ah[3], kh[0], kh[1]);
                mma_bf16(sacc[ng],     ah[0], ah[1], ah[2], ah[3], kl[0], kl[1]);
                mma_bf16(sacc[ng],     al[0], al[1], al[2], al[3], kh[0], kh[1]);
                mma_bf16(sacc[ng + 1], ah[0], ah[1], ah[2], ah[3], kh[2], kh[3]);
                mma_bf16(sacc[ng + 1], ah[0], ah[1], ah[2], ah[3], kl[2], kl[3]);
                mma_bf16(sacc[ng + 1], al[0], al[1], al[2], al[3], kh[2], kh[3]);
            }
        }

        // ---- mask + online softmax (q pre-scaled by 0.125) ----
        float mx0 = -INFINITY, mx1 = -INFINITY;
#pragma unroll
        for (int nf = 0; nf < 16; nf++)
#pragma unroll
            for (int e = 0; e < 4; e++) {
                const int rel = ch * 128 + nf * 8 + ((lane & 3) << 1) + (e & 1);
                const int r   = (e < 2) ? r_lo : r_hi;
                const bool valid = (rel >= r + 1) && (rel <= r + 128)
                                   && (q0 - 128 + rel >= 0);
                if (!valid) sacc[nf][e] = -INFINITY;
                else if (e < 2) mx0 = fmaxf(mx0, sacc[nf][e]);
                else            mx1 = fmaxf(mx1, sacc[nf][e]);
            }
        mx0 = fmaxf(mx0, __shfl_xor_sync(0xffffffffu, mx0, 1));
        mx0 = fmaxf(mx0, __shfl_xor_sync(0xffffffffu, mx0, 2));
        mx1 = fmaxf(mx1, __shfl_xor_sync(0xffffffffu, mx1, 1));
        mx1 = fmaxf(mx1, __shfl_xor_sync(0xffffffffu, mx1, 2));

        const float mn0 = fmaxf(m0, mx0), mn1 = fmaxf(m1, mx1);
        const float ms0 = (mn0 == -INFINITY) ? 0.f : mn0;
        const float ms1 = (mn1 == -INFINITY) ? 0.f : mn1;
        const float alpha0 = __expf(m0 - ms0);      // m0=-inf -> 0
        const float alpha1 = __expf(m1 - ms1);
        m0 = mn0; m1 = mn1;

        float s0 = 0.f, s1 = 0.f;
#pragma unroll
        for (int nf = 0; nf < 16; nf++)
#pragma unroll
            for (int e = 0; e < 4; e++) {
                const float p = __expf(sacc[nf][e] - ((e < 2) ? ms0 : ms1));
                sacc[nf][e] = p;
                if (e < 2) s0 += p; else s1 += p;
            }
        s0 += __shfl_xor_sync(0xffffffffu, s0, 1);
        s0 += __shfl_xor_sync(0xffffffffu, s0, 2);
        s1 += __shfl_xor_sync(0xffffffffu, s1, 1);
        s1 += __shfl_xor_sync(0xffffffffu, s1, 2);
        l0 = l0 * alpha0 + s0;
        l1 = l1 * alpha1 + s1;
#pragma unroll
        for (int nf = 0; nf < 8; nf++) {
            oacc[nf][0] *= alpha0; oacc[nf][1] *= alpha0;
            oacc[nf][2] *= alpha1; oacc[nf][3] *= alpha1;
        }

        // ---- O += P @ V (split P, split V) ----
#pragma unroll
        for (int ks2 = 0; ks2 < 8; ks2++) {
            const int nf = ks2 * 2;
            uint32_t ph[4], pl[4];
            packsplit(sacc[nf][0],     sacc[nf][1],     ph[0], pl[0]);
            packsplit(sacc[nf][2],     sacc[nf][3],     ph[1], pl[1]);
            packsplit(sacc[nf + 1][0], sacc[nf + 1][1], ph[2], pl[2]);
            packsplit(sacc[nf + 1][2], sacc[nf + 1][3], ph[3], pl[3]);
#pragma unroll
            for (int dg = 0; dg < 4; dg++) {
                const uint32_t rv = sb + 2 * (VH0
                    + (ch * 128 + ks2 * 16 + (lane & 15)) * APITCH
                    + dg * 16 + ((lane >> 4) << 3));
                uint32_t vh[4], vl[4];
                LDSM4T(vh[0], vh[1], vh[2], vh[3], rv);
                LDSM4T(vl[0], vl[1], vl[2], vl[3], rv + 2 * (VL0 - VH0));
                mma_bf16(oacc[2 * dg],     ph[0], ph[1], ph[2], ph[3], vh[0], vh[1]);
                mma_bf16(oacc[2 * dg],     pl[0], pl[1], pl[2], pl[3], vh[0], vh[1]);
                mma_bf16(oacc[2 * dg],     ph[0], ph[1], ph[2], ph[3], vl[0], vl[1]);
                mma_bf16(oacc[2 * dg + 1], ph[0], ph[1], ph[2], ph[3], vh[2], vh[3]);
                mma_bf16(oacc[2 * dg + 1], pl[0], pl[1], pl[2], pl[3], vh[2], vh[3]);
                mma_bf16(oacc[2 * dg + 1], ph[0], ph[1], ph[2], ph[3], vl[2], vl[3]);
            }
        }
    }

    // ---- epilogue: normalize, split to bf16 hi/lo, write [b*T+t, h*64+d] ----
    const float i0 = 1.0f / l0, i1 = 1.0f / l1;
    const int qi0 = q0 + r_lo, qi1 = q0 + r_hi;
#pragma unroll
    for (int nf = 0; nf < 8; nf++) {
        const int d0 = nf * 8 + ((lane & 3) << 1);
        const size_t off0 = ((size_t)b * TLEN + qi0) * D_MODEL + h * 64 + d0;
        const size_t off1 = ((size_t)b * TLEN + qi1) * D_MODEL + h * 64 + d0;
        uint32_t uh, ul;
        packsplit(oacc[nf][0] * i0, oacc[nf][1] * i0, uh, ul);
        *(uint32_t*)(g_ah + off0) = uh;
        *(uint32_t*)(g_al + off0) = ul;
        packsplit(oacc[nf][2] * i1, oacc[nf][3] * i1, uh, ul);
        *(uint32_t*)(g_ah + off1) = uh;
        *(uint32_t*)(g_al + off1) = ul;
    }
}

// ---------------------------------------------------------------------------
extern "C" void kernel_launch(void* const* d_in, const int* in_sizes, int n_in,
                              void* d_out, int out_size)
{
    const float* query = (const float*)d_in[0];
    const float* Wq    = (const float*)d_in[1];
    const float* Wk    = (const float*)d_in[2];
    const float* Wv    = (const float*)d_in[3];
    const float* Wo    = (const float*)d_in[4];
    const float* bo    = (const float*)d_in[5];
    float* out = (float*)d_out;

    cudaFuncSetAttribute(tc_gemm<1>,
                         cudaFuncAttributeMaxDynamicSharedMemorySize, GSMEM);
    cudaFuncSetAttribute(tc_gemm<0>,
                         cudaFuncAttributeMaxDynamicSharedMemorySize, GSMEM);
    cudaFuncSetAttribute(attn_mma,
                         cudaFuncAttributeMaxDynamicSharedMemorySize, ASMEM);

    const int nq4 = QKV_N / 4, nw4 = (D_MODEL * D_MODEL) / 4;

    // 1) split inputs into bf16 hi/lo
    split_kernel<0><<<nq4 / 256, 256>>>(query, nq4);
    split_kernel<1><<<nw4 / 256, 256>>>(Wq, nw4);
    split_kernel<2><<<nw4 / 256, 256>>>(Wk, nw4);
    split_kernel<3><<<nw4 / 256, 256>>>(Wv, nw4);
    split_kernel<4><<<nw4 / 256, 256>>>(Wo, nw4);

    // 2) QKV projections (+fused rope/scale/split epilogue)
    tc_gemm<1><<<dim3(D_MODEL / 128, MROWS / 128, 3), 256, GSMEM>>>(nullptr, nullptr);

    // 3) tensor-core sliding-window attention (writes ah/al splits)
    attn_mma<<<dim3(TLEN / 128, N_HEADS, BATCH), 256, ASMEM>>>();

    // 4) output projection + bias
    tc_gemm<0><<<dim3(D_MODEL / 128, MROWS / 128, 1), 256, GSMEM>>>(bo, out);
}

// round 15
// speedup vs baseline: 1.7275x; 1.7275x over previous
#include <cuda_runtime.h>
#include <cuda_bf16.h>
#include <cstdint>
#include <math.h>

#define D_MODEL   1024
#define N_HEADS   16
#define HEAD_DIM  64
#define BATCH     2
#define TLEN      2048
#define WINDOW    128
#define MROWS     (BATCH * TLEN)          // 4096
#define QKV_N     (MROWS * D_MODEL)       // 4194304

// bf16 scratch
__device__ __nv_bfloat16 g_qh[QKV_N], g_ql[QKV_N];          // input query split
__device__ __nv_bfloat16 g_wh[4][D_MODEL * D_MODEL];
__device__ __nv_bfloat16 g_wl[4][D_MODEL * D_MODEL];
__device__ __nv_bfloat16 g_ah[QKV_N], g_al[QKV_N];          // attn out split
// rope'd q (pre-scaled), k, v splits in [b,h,t,d]
__device__ __nv_bfloat16 g_xqh[QKV_N], g_xql[QKV_N];
__device__ __nv_bfloat16 g_xkh[QKV_N], g_xkl[QKV_N];
__device__ __nv_bfloat16 g_xvh[QKV_N], g_xvl[QKV_N];

// ---------------------------------------------------------------------------
__device__ __forceinline__ uint32_t smem_u32(const void* p) {
    uint32_t a;
    asm("{ .reg .u64 t; cvta.to.shared.u64 t, %1; cvt.u32.u64 %0, t; }"
        : "=r"(a) : "l"(p));
    return a;
}

#define CP_ASYNC16(dst, src) \
    asm volatile("cp.async.cg.shared.global [%0], [%1], 16;" :: "r"(dst), "l"(src))
#define CP_COMMIT()  asm volatile("cp.async.commit_group;" ::: "memory")
#define CP_WAIT(n)   asm volatile("cp.async.wait_group %0;" :: "n"(n) : "memory")

#define LDSM4(r0, r1, r2, r3, a) \
    asm volatile("ldmatrix.sync.aligned.m8n8.x4.shared.b16 {%0,%1,%2,%3}, [%4];" \
                 : "=r"(r0), "=r"(r1), "=r"(r2), "=r"(r3) : "r"(a))
#define LDSM4T(r0, r1, r2, r3, a) \
    asm volatile("ldmatrix.sync.aligned.m8n8.x4.trans.shared.b16 {%0,%1,%2,%3}, [%4];" \
                 : "=r"(r0), "=r"(r1), "=r"(r2), "=r"(r3) : "r"(a))

__device__ __forceinline__ void mma_bf16(float* d, uint32_t a0, uint32_t a1,
                                         uint32_t a2, uint32_t a3,
                                         uint32_t b0, uint32_t b1) {
    asm volatile(
        "mma.sync.aligned.m16n8k16.row.col.f32.bf16.bf16.f32 "
        "{%0,%1,%2,%3}, {%4,%5,%6,%7}, {%8,%9}, {%0,%1,%2,%3};"
        : "+f"(d[0]), "+f"(d[1]), "+f"(d[2]), "+f"(d[3])
        : "r"(a0), "r"(a1), "r"(a2), "r"(a3), "r"(b0), "r"(b1));
}

__device__ __forceinline__ void packsplit(float x, float y,
                                          uint32_t& h, uint32_t& l) {
    __nv_bfloat16 hx = __float2bfloat16(x), hy = __float2bfloat16(y);
    __nv_bfloat16 lx = __float2bfloat16(x - __bfloat162float(hx));
    __nv_bfloat16 ly = __float2bfloat16(y - __bfloat162float(hy));
    h = (uint32_t)__bfloat16_as_ushort(hx) | ((uint32_t)__bfloat16_as_ushort(hy) << 16);
    l = (uint32_t)__bfloat16_as_ushort(lx) | ((uint32_t)__bfloat16_as_ushort(ly) << 16);
}

// ---------------------------------------------------------------------------
// fp32 -> (bf16 hi, bf16 lo) split: 0=query, 1..4=W
// ---------------------------------------------------------------------------
template <int DST>
__global__ __launch_bounds__(256) void split_kernel(const float* __restrict__ src, int n4)
{
    __nv_bfloat16 *dh, *dl;
    if (DST == 0) { dh = g_qh; dl = g_ql; }
    else          { dh = g_wh[DST - 1]; dl = g_wl[DST - 1]; }
    const int i = blockIdx.x * 256 + threadIdx.x;
    if (i >= n4) return;
    float4 x = ((const float4*)src)[i];
    uint32_t h0, l0, h1, l1;
    packsplit(x.x, x.y, h0, l0);
    packsplit(x.z, x.w, h1, l1);
    ((uint2*)dh)[i] = make_uint2(h0, h1);
    ((uint2*)dl)[i] = make_uint2(l0, l1);
}

// ---------------------------------------------------------------------------
// bf16 mma.sync split GEMM (validated R11). NOW __launch_bounds__(256,2):
// cap 128 regs -> 2 CTAs/SM to hide cp.async latency.
// ---------------------------------------------------------------------------
#define PITCH   40
#define MATSZ   (128 * PITCH)
#define STAGEB  (4 * MATSZ * 2)
#define GSMEM   (2 * STAGEB)

template <int MODE>
__global__ __launch_bounds__(256, 2) void tc_gemm(const float* __restrict__ bias,
                                                  float* __restrict__ Cout)
{
    extern __shared__ __nv_bfloat16 sm[];
    const uint32_t sb = smem_u32(sm);
    const int tid  = threadIdx.x;
    const int lane = tid & 31, warp = tid >> 5;
    const int z    = (MODE == 1) ? blockIdx.z : 3;
    const int m0   = blockIdx.y * 128;
    const int n0   = blockIdx.x * 128;
    const int wm   = (warp >> 1) * 32;
    const int wn   = (warp & 1) * 64;

    const __nv_bfloat16* Ah = (MODE == 1) ? g_qh : g_ah;
    const __nv_bfloat16* Al = (MODE == 1) ? g_ql : g_al;
    const __nv_bfloat16* Wh = g_wh[z];
    const __nv_bfloat16* Wl = g_wl[z];
    const __nv_bfloat16* mats[4] = {Ah, Al, Wh, Wl};

    float acc[2][8][4];
#pragma unroll
    for (int mi = 0; mi < 2; mi++)
#pragma unroll
        for (int ni = 0; ni < 8; ni++)
#pragma unroll
            for (int e = 0; e < 4; e++) acc[mi][ni][e] = 0.f;

    auto load_stage = [&](int buf, int k0) {
#pragma unroll
        for (int it = 0; it < 8; it++) {
            const int i   = tid + it * 256;
            const int mat = i >> 9;
            const int r   = (i >> 2) & 127;
            const int c4  = i & 3;
            const uint32_t dst = sb + buf * STAGEB +
                                 (mat * MATSZ + r * PITCH + c4 * 8) * 2;
            const int grow = (mat < 2) ? (m0 + r) : (n0 + r);
            const __nv_bfloat16* src = mats[mat] + (size_t)grow * D_MODEL + k0 + c4 * 8;
            CP_ASYNC16(dst, src);
        }
        CP_COMMIT();
    };

    load_stage(0, 0);

    for (int ch = 0; ch < 32; ch++) {
        const int buf = ch & 1;
        if (ch + 1 < 32) load_stage(buf ^ 1, (ch + 1) * 32);
        if (ch + 1 < 32) CP_WAIT(1); else CP_WAIT(0);
        __syncthreads();

        const uint32_t base = sb + buf * STAGEB;
#pragma unroll
        for (int ks = 0; ks < 2; ks++) {
            const int kk = ks * 16;
            uint32_t ah[2][4], al[2][4];
#pragma unroll
            for (int mi = 0; mi < 2; mi++) {
                const uint32_t ra = (uint32_t)((wm + mi * 16 + (lane & 15)) * PITCH
                                    + kk + ((lane >> 4) << 3)) * 2;
                LDSM4(ah[mi][0], ah[mi][1], ah[mi][2], ah[mi][3], base + 0 * MATSZ * 2 + ra);
                LDSM4(al[mi][0], al[mi][1], al[mi][2], al[mi][3], base + 1 * MATSZ * 2 + ra);
            }
            uint32_t bh[8][2], bl[8][2];
#pragma unroll
            for (int ng = 0; ng < 8; ng += 2) {
                const uint32_t rb = (uint32_t)((wn + ng * 8 + (lane & 7) + ((lane >> 4) << 3)) * PITCH
                                    + kk + (((lane >> 3) & 1) << 3)) * 2;
                LDSM4(bh[ng][0], bh[ng][1], bh[ng + 1][0], bh[ng + 1][1],
                      base + 2 * MATSZ * 2 + rb);
                LDSM4(bl[ng][0], bl[ng][1], bl[ng + 1][0], bl[ng + 1][1],
                      base + 3 * MATSZ * 2 + rb);
            }
#pragma unroll
            for (int mi = 0; mi < 2; mi++)
#pragma unroll
                for (int ni = 0; ni < 8; ni++) {
                    mma_bf16(acc[mi][ni], ah[mi][0], ah[mi][1], ah[mi][2], ah[mi][3],
                             bh[ni][0], bh[ni][1]);
                    mma_bf16(acc[mi][ni], ah[mi][0], ah[mi][1], ah[mi][2], ah[mi][3],
                             bl[ni][0], bl[ni][1]);
                    mma_bf16(acc[mi][ni], al[mi][0], al[mi][1], al[mi][2], al[mi][3],
                             bh[ni][0], bh[ni][1]);
                }
        }
        __syncthreads();
    }

    // ---- epilogue ----
    const float coef = -logf(10000.0f) / 32.0f;
#pragma unroll
    for (int mi = 0; mi < 2; mi++) {
#pragma unroll
        for (int r8 = 0; r8 < 2; r8++) {
            const int m = m0 + wm + mi * 16 + (lane >> 2) + r8 * 8;
            const int t = m & (TLEN - 1);
            const int b = m >> 11;

            if (MODE == 1) {
                if (z < 2) {
#pragma unroll
                    for (int ni = 0; ni < 4; ni++)
#pragma unroll
                        for (int e = 0; e < 2; e++) {
                            const int dd = ni * 8 + ((lane & 3) << 1) + e;
                            float sn, cs;
                            sincosf((float)t * expf((float)dd * coef), &sn, &cs);
                            const float x0 = acc[mi][ni][r8 * 2 + e];
                            const float x1 = acc[mi][ni + 4][r8 * 2 + e];
                            acc[mi][ni][r8 * 2 + e]     = x0 * cs - x1 * sn;
                            acc[mi][ni + 4][r8 * 2 + e] = x1 * cs + x0 * sn;
                        }
                }
                __nv_bfloat16* dh = (z == 0) ? g_xqh : (z == 1) ? g_xkh : g_xvh;
                __nv_bfloat16* dl = (z == 0) ? g_xql : (z == 1) ? g_xkl : g_xvl;
                const float sc = (z == 0) ? 0.125f : 1.0f;   // fold sm_scale into q
                const int h = blockIdx.x * 2 + (warp & 1);
                const size_t off = (((size_t)b * N_HEADS + h) * TLEN + t) * HEAD_DIM;
#pragma unroll
                for (int ni = 0; ni < 8; ni++) {
                    const int d0 = ni * 8 + ((lane & 3) << 1);
                    uint32_t uh, ul;
                    packsplit(acc[mi][ni][r8 * 2] * sc, acc[mi][ni][r8 * 2 + 1] * sc, uh, ul);
                    *(uint32_t*)(dh + off + d0) = uh;
                    *(uint32_t*)(dl + off + d0) = ul;
                }
            } else {
                const size_t off = (size_t)m * D_MODEL + n0 + wn;
#pragma unroll
                for (int ni = 0; ni < 8; ni++) {
                    const int d0 = ni * 8 + ((lane & 3) << 1);
                    *(float2*)&Cout[off + d0] =
                        make_float2(acc[mi][ni][r8 * 2]     + __ldg(&bias[n0 + wn + d0]),
                                    acc[mi][ni][r8 * 2 + 1] + __ldg(&bias[n0 + wn + d0 + 1]));
                }
            }
        }
    }
}

// ---------------------------------------------------------------------------
// Tensor-core sliding-window attention + PER-WARP TILE SKIPS.
// Warp w's rows span [w*16, w*16+15] -> valid key rel range
// [w*16+1, w*16+143]; tiles fully outside are skipped in S (16-key),
// mask/exp (8-key), and PV (16-key) phases -> ~40% work removed, bit-exact.
// ---------------------------------------------------------------------------
#define APITCH 72
#define QH0 0
#define QL0 9216          // 128*72
#define KH0 18432
#define KL0 36864
#define VH0 55296
#define VL0 73728
#define ASMEM (92160 * 2) // 184320 B

__global__ __launch_bounds__(256, 1) void attn_mma()
{
    extern __shared__ __nv_bfloat16 smA[];
    const uint32_t sb = smem_u32(smA);
    const int tid = threadIdx.x, lane = tid & 31, w = tid >> 5;
    const int q0 = blockIdx.x * 128;
    const int h  = blockIdx.y, b = blockIdx.z;
    const size_t hb = ((size_t)b * N_HEADS + h) * TLEN;

    // ---- load Q (128 rows) and K/V window (256 rows) ----
    {
        const __nv_bfloat16* srcQ[2]  = {g_xqh, g_xql};
        const __nv_bfloat16* srcKV[4] = {g_xkh, g_xkl, g_xvh, g_xvl};
#pragma unroll
        for (int it = 0; it < 8; it++) {
            const int idx = tid + it * 256;
            const int mat = idx >> 10, r = (idx >> 3) & 127, c = idx & 7;
            uint4 v = *(const uint4*)(srcQ[mat] + (hb + q0 + r) * 64 + c * 8);
            *(uint4*)(smA + mat * QL0 + r * APITCH + c * 8) = v;
        }
#pragma unroll
        for (int it = 0; it < 32; it++) {
            const int idx = tid + it * 256;
            const int mat = idx >> 11, r = (idx >> 3) & 255, c = idx & 7;
            const int j = q0 - 128 + r;
            uint4 v = make_uint4(0u, 0u, 0u, 0u);
            if (j >= 0) v = *(const uint4*)(srcKV[mat] + (hb + j) * 64 + c * 8);
            *(uint4*)(smA + KH0 + mat * 18432 + r * APITCH + c * 8) = v;
        }
    }
    __syncthreads();

    float oacc[8][4];
#pragma unroll
    for (int nf = 0; nf < 8; nf++)
#pragma unroll
        for (int e = 0; e < 4; e++) oacc[nf][e] = 0.f;
    float m0 = -INFINITY, m1 = -INFINITY, l0 = 0.f, l1 = 0.f;
    const int r_lo = w * 16 + (lane >> 2), r_hi = r_lo + 8;
    const int lo_lim = w * 16 + 1;          // min valid key rel for this warp
    const int hi_lim = w * 16 + 143;        // max valid key rel for this warp

    for (int ch = 0; ch < 2; ch++) {
        // ---- S = Q @ K^T (split), with 16-key tile skip ----
        float sacc[16][4];
#pragma unroll
        for (int nf = 0; nf < 16; nf++)
#pragma unroll
            for (int e = 0; e < 4; e++) sacc[nf][e] = 0.f;

#pragma unroll
        for (int ks = 0; ks < 4; ks++) {
            const int kk = ks * 16;
            uint32_t ah[4], al[4];
            const uint32_t ra = sb + 2 * ((w * 16 + (lane & 15)) * APITCH
                                          + kk + ((lane >> 4) << 3));
            LDSM4(ah[0], ah[1], ah[2], ah[3], ra);
            LDSM4(al[0], al[1], al[2], al[3], ra + 2 * QL0);
#pragma unroll
            for (int ng = 0; ng < 16; ng += 2) {
                const int t0 = ch * 128 + ng * 8;
                if (t0 + 15 < lo_lim || t0 > hi_lim) continue;   // fully masked
                const uint32_t rb = sb + 2 * (KH0
                    + (ch * 128 + ng * 8 + (lane & 7) + ((lane >> 4) << 3)) * APITCH
                    + kk + (((lane >> 3) & 1) << 3));
                uint32_t kh[4], kl[4];
                LDSM4(kh[0], kh[1], kh[2], kh[3], rb);
                LDSM4(kl[0], kl[1], kl[2], kl[3], rb + 2 * (KL0 - KH0));
                mma_bf16(sacc[ng],     ah[0], ah[1], ah[2], ah[3], kh[0], kh[1]);
                mma_bf16(sacc[ng],     ah[0], ah[1], ah[2], ah[3], kl[0], kl[1]);
                mma_bf16(sacc[ng],     al[0], al[1], al[2], al[3], kh[0], kh[1]);
                mma_bf16(sacc[ng + 1], ah[0], ah[1], ah[2], ah[3], kh[2], kh[3]);
                mma_bf16(sacc[ng + 1], ah[0], ah[1], ah[2], ah[3], kl[2], kl[3]);
                mma_bf16(sacc[ng + 1], al[0], al[1], al[2], al[3], kh[2], kh[3]);
            }
        }

        // ---- mask + max (8-key tile skip) ----
        float mx0 = -INFINITY, mx1 = -INFINITY;
#pragma unroll
        for (int nf = 0; nf < 16; nf++) {
            const int t0 = ch * 128 + nf * 8;
            if (t0 + 7 < lo_lim || t0 > hi_lim) continue;        // dead tile
#pragma unroll
            for (int e = 0; e < 4; e++) {
                const int rel = t0 + ((lane & 3) << 1) + (e & 1);
                const int r   = (e < 2) ? r_lo : r_hi;
                const bool valid = (rel >= r + 1) && (rel <= r + 128)
                                   && (q0 - 128 + rel >= 0);
                if (!valid) sacc[nf][e] = -INFINITY;
                else if (e < 2) mx0 = fmaxf(mx0, sacc[nf][e]);
                else            mx1 = fmaxf(mx1, sacc[nf][e]);
            }
        }
        mx0 = fmaxf(mx0, __shfl_xor_sync(0xffffffffu, mx0, 1));
        mx0 = fmaxf(mx0, __shfl_xor_sync(0xffffffffu, mx0, 2));
        mx1 = fmaxf(mx1, __shfl_xor_sync(0xffffffffu, mx1, 1));
        mx1 = fmaxf(mx1, __shfl_xor_sync(0xffffffffu, mx1, 2));

        const float mn0 = fmaxf(m0, mx0), mn1 = fmaxf(m1, mx1);
        const float ms0 = (mn0 == -INFINITY) ? 0.f : mn0;
        const float ms1 = (mn1 == -INFINITY) ? 0.f : mn1;
        const float alpha0 = __expf(m0 - ms0);
        const float alpha1 = __expf(m1 - ms1);
        m0 = mn0; m1 = mn1;

        // ---- exp (8-key tile skip; dead tiles forced to p=0) ----
        float s0 = 0.f, s1 = 0.f;
#pragma unroll
        for (int nf = 0; nf < 16; nf++) {
            const int t0 = ch * 128 + nf * 8;
            if (t0 + 7 < lo_lim || t0 > hi_lim) {
                sacc[nf][0] = sacc[nf][1] = sacc[nf][2] = sacc[nf][3] = 0.f;
                continue;
            }
#pragma unroll
            for (int e = 0; e < 4; e++) {
                const float p = __expf(sacc[nf][e] - ((e < 2) ? ms0 : ms1));
                sacc[nf][e] = p;
                if (e < 2) s0 += p; else s1 += p;
            }
        }
        s0 += __shfl_xor_sync(0xffffffffu, s0, 1);
        s0 += __shfl_xor_sync(0xffffffffu, s0, 2);
        s1 += __shfl_xor_sync(0xffffffffu, s1, 1);
        s1 += __shfl_xor_sync(0xffffffffu, s1, 2);
        l0 = l0 * alpha0 + s0;
        l1 = l1 * alpha1 + s1;
#pragma unroll
        for (int nf = 0; nf < 8; nf++) {
            oacc[nf][0] *= alpha0; oacc[nf][1] *= alpha0;
            oacc[nf][2] *= alpha1; oacc[nf][3] *= alpha1;
        }

        // ---- O += P @ V (split P, split V), 16-key tile skip ----
#pragma unroll
        for (int ks2 = 0; ks2 < 8; ks2++) {
            const int t0 = ch * 128 + ks2 * 16;
            if (t0 + 15 < lo_lim || t0 > hi_lim) continue;       // p == 0 here
            const int nf = ks2 * 2;
            uint32_t ph[4], pl[4];
            packsplit(sacc[nf][0],     sacc[nf][1],     ph[0], pl[0]);
            packsplit(sacc[nf][2],     sacc[nf][3],     ph[1], pl[1]);
            packsplit(sacc[nf + 1][0], sacc[nf + 1][1], ph[2], pl[2]);
            packsplit(sacc[nf + 1][2], sacc[nf + 1][3], ph[3], pl[3]);
#pragma unroll
            for (int dg = 0; dg < 4; dg++) {
                const uint32_t rv = sb + 2 * (VH0
                    + (ch * 128 + ks2 * 16 + (lane & 15)) * APITCH
                    + dg * 16 + ((lane >> 4) << 3));
                uint32_t vh[4], vl[4];
                LDSM4T(vh[0], vh[1], vh[2], vh[3], rv);
                LDSM4T(vl[0], vl[1], vl[2], vl[3], rv + 2 * (VL0 - VH0));
                mma_bf16(oacc[2 * dg],     ph[0], ph[1], ph[2], ph[3], vh[0], vh[1]);
                mma_bf16(oacc[2 * dg],     pl[0], pl[1], pl[2], pl[3], vh[0], vh[1]);
                mma_bf16(oacc[2 * dg],     ph[0], ph[1], ph[2], ph[3], vl[0], vl[1]);
                mma_bf16(oacc[2 * dg + 1], ph[0], ph[1], ph[2], ph[3], vh[2], vh[3]);
                mma_bf16(oacc[2 * dg + 1], pl[0], pl[1], pl[2], pl[3], vh[2], vh[3]);
                mma_bf16(oacc[2 * dg + 1], ph[0], ph[1], ph[2], ph[3], vl[2], vl[3]);
            }
        }
    }

    // ---- epilogue: normalize, split to bf16 hi/lo, write [b*T+t, h*64+d] ----
    const float i0 = 1.0f / l0, i1 = 1.0f / l1;
    const int qi0 = q0 + r_lo, qi1 = q0 + r_hi;
#pragma unroll
    for (int nf = 0; nf < 8; nf++) {
        const int d0 = nf * 8 + ((lane & 3) << 1);
        const size_t off0 = ((size_t)b * TLEN + qi0) * D_MODEL + h * 64 + d0;
        const size_t off1 = ((size_t)b * TLEN + qi1) * D_MODEL + h * 64 + d0;
        uint32_t uh, ul;
        packsplit(oacc[nf][0] * i0, oacc[nf][1] * i0, uh, ul);
        *(uint32_t*)(g_ah + off0) = uh;
        *(uint32_t*)(g_al + off0) = ul;
        packsplit(oacc[nf][2] * i1, oacc[nf][3] * i1, uh, ul);
        *(uint32_t*)(g_ah + off1) = uh;
        *(uint32_t*)(g_al + off1) = ul;
    }
}

// ---------------------------------------------------------------------------
extern "C" void kernel_launch(void* const* d_in, const int* in_sizes, int n_in,
                              void* d_out, int out_size)
{
    const float* query = (const float*)d_in[0];
    const float* Wq    = (const float*)d_in[1];
    const float* Wk    = (const float*)d_in[2];
    const float* Wv    = (const float*)d_in[3];
    const float* Wo    = (const float*)d_in[4];
    const float* bo    = (const float*)d_in[5];
    float* out = (float*)d_out;

    cudaFuncSetAttribute(tc_gemm<1>,
                         cudaFuncAttributeMaxDynamicSharedMemorySize, GSMEM);
    cudaFuncSetAttribute(tc_gemm<0>,
                         cudaFuncAttributeMaxDynamicSharedMemorySize, GSMEM);
    cudaFuncSetAttribute(attn_mma,
                         cudaFuncAttributeMaxDynamicSharedMemorySize, ASMEM);

    const int nq4 = QKV_N / 4, nw4 = (D_MODEL * D_MODEL) / 4;

    // 1) split inputs into bf16 hi/lo
    split_kernel<0><<<nq4 / 256, 256>>>(query, nq4);
    split_kernel<1><<<nw4 / 256, 256>>>(Wq, nw4);
    split_kernel<2><<<nw4 / 256, 256>>>(Wk, nw4);
    split_kernel<3><<<nw4 / 256, 256>>>(Wv, nw4);
    split_kernel<4><<<nw4 / 256, 256>>>(Wo, nw4);

    // 2) QKV projections (+fused rope/scale/split epilogue)
    tc_gemm<1><<<dim3(D_MODEL / 128, MROWS / 128, 3), 256, GSMEM>>>(nullptr, nullptr);

    // 3) tensor-core sliding-window attention (tile-skip, writes ah/al splits)
    attn_mma<<<dim3(TLEN / 128, N_HEADS, BATCH), 256, ASMEM>>>();

    // 4) output projection + bias
    tc_gemm<0><<<dim3(D_MODEL / 128, MROWS / 128, 1), 256, GSMEM>>>(bo, out);
}